// round 8
// baseline (speedup 1.0000x reference)
#include <cuda_runtime.h>
#include <cuda_fp16.h>
#include <cstdint>

#define NE 8
#define DMODEL 1024
#define DFF 4096
#define TTOK 2048
#define NSPLIT 4

// ---------------- scratch ----------------
__device__ int g_perm[TTOK];
__device__ int g_off[NE + 1];
__device__ __align__(16) __half g_x16[(size_t)TTOK * DMODEL];
__device__ __align__(16) __half g_h[(size_t)TTOK * DFF];
__device__ __align__(16) float g_part[NSPLIT][TTOK][DMODEL];

// ---------------- helpers ----------------
__device__ __forceinline__ uint32_t s2u(const void* p) {
    return (uint32_t)__cvta_generic_to_shared(p);
}
__device__ __forceinline__ void cpa(uint32_t d, const void* s, int sz) {
    asm volatile("cp.async.cg.shared.global [%0], [%1], 16, %2;" :: "r"(d), "l"(s), "r"(sz));
}
__device__ __forceinline__ void cp_commit() {
    asm volatile("cp.async.commit_group;");
}
__device__ __forceinline__ void cp_wait1() {
    asm volatile("cp.async.wait_group 1;");
}
__device__ __forceinline__ void ldsm4(uint32_t* r, uint32_t a) {
    asm volatile("ldmatrix.sync.aligned.m8n8.x4.shared.b16 {%0,%1,%2,%3}, [%4];"
                 : "=r"(r[0]), "=r"(r[1]), "=r"(r[2]), "=r"(r[3]) : "r"(a));
}
__device__ __forceinline__ void ldsm4t(uint32_t* r, uint32_t a) {
    asm volatile("ldmatrix.sync.aligned.m8n8.x4.trans.shared.b16 {%0,%1,%2,%3}, [%4];"
                 : "=r"(r[0]), "=r"(r[1]), "=r"(r[2]), "=r"(r[3]) : "r"(a));
}
__device__ __forceinline__ void mma16(float* c, const uint32_t* a, uint32_t b0, uint32_t b1) {
    asm volatile("mma.sync.aligned.m16n8k16.row.col.f32.f16.f16.f32 "
                 "{%0,%1,%2,%3},{%4,%5,%6,%7},{%8,%9},{%0,%1,%2,%3};"
                 : "+f"(c[0]), "+f"(c[1]), "+f"(c[2]), "+f"(c[3])
                 : "r"(a[0]), "r"(a[1]), "r"(a[2]), "r"(a[3]), "r"(b0), "r"(b1));
}
__device__ __forceinline__ void sts_f4h(char* base, int id, float4 v) {
    int r = id >> 4, c = id & 15;
    __half2* d = (__half2*)(base + r * 144 + c * 8);
    d[0] = __floats2half2_rn(v.x, v.y);
    d[1] = __floats2half2_rn(v.z, v.w);
}

// ---------------- kernel 1: bucket tokens by expert ----------------
__global__ void moe_build_perm(const void* eidx_raw) {
    __shared__ int cnt[NE], base[NE], nz;
    int t = threadIdx.x;
    if (t < NE) cnt[t] = 0;
    if (t == 0) nz = 0;
    __syncthreads();
    const int* i32 = (const int*)eidx_raw;
    for (int i = t; i < TTOK / 2; i += blockDim.x)
        if (i32[2 * i + 1] != 0) atomicOr(&nz, 1);
    __syncthreads();
    bool is64 = (nz == 0);
    const long long* i64 = (const long long*)eidx_raw;
    for (int i = t; i < TTOK; i += blockDim.x)
        atomicAdd(&cnt[is64 ? (int)i64[i] : i32[i]], 1);
    __syncthreads();
    if (t == 0) {
        int s = 0;
        for (int e = 0; e < NE; e++) { g_off[e] = s; base[e] = s; s += cnt[e]; }
        g_off[NE] = s;
    }
    __syncthreads();
    for (int i = t; i < TTOK; i += blockDim.x) {
        int e = is64 ? (int)i64[i] : i32[i];
        g_perm[atomicAdd(&base[e], 1)] = i;
    }
}

// ---------------- kernel 2: gather + fp16 convert ----------------
__global__ void moe_gather(const float* __restrict__ x) {
    int src = g_perm[blockIdx.x];
    float4 v = ((const float4*)(x + (size_t)src * DMODEL))[threadIdx.x];
    __half2* d = (__half2*)(g_x16 + (size_t)blockIdx.x * DMODEL + threadIdx.x * 4);
    d[0] = __floats2half2_rn(v.x, v.y);
    d[1] = __floats2half2_rn(v.z, v.w);
}

#define G1_A    0
#define G1_BG16 30720
#define G1_BU16 39936
#define G1_SMEM 49152
#define G2_A   0
#define G2_B16 30720
#define G2_SMEM 39936

// ---------------- kernel 3: gate+up GEMM + SwiGLU ----------------
// grid: (x = mtile, y = n-tile, z = expert) — m-tiles sharing weights adjacent
__global__ void __launch_bounds__(256, 2)
moe_gateup(const float* __restrict__ wg, const float* __restrict__ wu) {
    extern __shared__ char smem[];
    const int e = blockIdx.z, seg = g_off[e], cnt = g_off[e + 1] - seg;
    const int mtile = blockIdx.x;
    if (mtile * 128 >= cnt) return;
    const int m0g = seg + mtile * 128, n0 = blockIdx.y * 64;

    const int tid = threadIdx.x, warp = tid >> 5, lane = tid & 31;
    const int wm = warp >> 1, wn = warp & 1;
    const uint32_t sb = s2u(smem);

    const float* wgp = wg + (size_t)e * DMODEL * DFF + n0;
    const float* wup = wu + (size_t)e * DMODEL * DFF + n0;

    auto stageA = [&](int s) {
        int slot = s % 3, k0 = s * 32;
        #pragma unroll
        for (int i = 0; i < 2; i++) {
            int id = tid + i * 256;
            int r = id >> 2, c = id & 3;
            bool ok = (mtile * 128 + r) < cnt;
            const __half* src = ok ? g_x16 + (size_t)(m0g + r) * DMODEL + k0 + c * 8 : g_x16;
            cpa(sb + G1_A + slot * 10240 + r * 80 + c * 16, src, ok ? 16 : 0);
        }
        cp_commit();
    };
    float4 rg[2], ru[2];
    auto ldB = [&](int s) {
        int k0 = s * 32;
        #pragma unroll
        for (int i = 0; i < 2; i++) {
            int id = tid + i * 256;
            int r = id >> 4, c = id & 15;
            size_t off = (size_t)(k0 + r) * DFF + c * 4;
            rg[i] = __ldg((const float4*)(wgp + off));
            ru[i] = __ldg((const float4*)(wup + off));
        }
    };
    auto stsB = [&](int s) {
        char* bg16 = smem + G1_BG16 + (s & 1) * 4608;
        char* bu16 = smem + G1_BU16 + (s & 1) * 4608;
        #pragma unroll
        for (int i = 0; i < 2; i++) {
            sts_f4h(bg16, tid + i * 256, rg[i]);
            sts_f4h(bu16, tid + i * 256, ru[i]);
        }
    };

    ldB(0);
    stageA(0);
    stageA(1);
    stsB(0);                          // B(0) in smem before first sync

    float cg[2][4][4] = {}, cu[2][4][4] = {};
    const int KT = DMODEL / 32;
    for (int s = 0; s < KT; s++) {
        const int b1 = s & 1, slot = s % 3;
        cp_wait1();
        __syncthreads();              // A(s) visible; STS(s) from prev iter visible
        if (s + 1 < KT) ldB(s + 1);   // regs free: stsB(s) already consumed them
        if (s + 2 < KT) stageA(s + 2);
        else cp_commit();
        uint32_t sA = sb + G1_A + slot * 10240;
        uint32_t sG = sb + G1_BG16 + b1 * 4608;
        uint32_t sU = sb + G1_BU16 + b1 * 4608;
        #pragma unroll
        for (int ks = 0; ks < 2; ks++) {
            uint32_t a[2][4], bg[8], bu[8];
            #pragma unroll
            for (int mt = 0; mt < 2; mt++) {
                int row = wm * 32 + mt * 16 + (lane & 15);
                int col = ks * 16 + (lane >> 4) * 8;
                ldsm4(a[mt], sA + row * 80 + col * 2);
            }
            #pragma unroll
            for (int h = 0; h < 2; h++) {
                int kr = ks * 16 + (lane & 15);
                int nc = wn * 32 + h * 16 + (lane >> 4) * 8;
                ldsm4t(&bg[h * 4], sG + kr * 144 + nc * 2);
                ldsm4t(&bu[h * 4], sU + kr * 144 + nc * 2);
            }
            #pragma unroll
            for (int mt = 0; mt < 2; mt++)
                #pragma unroll
                for (int nt = 0; nt < 4; nt++) {
                    mma16(cg[mt][nt], a[mt], bg[nt * 2], bg[nt * 2 + 1]);
                    mma16(cu[mt][nt], a[mt], bu[nt * 2], bu[nt * 2 + 1]);
                }
        }
        // late STS: LDG(s+1) -> consumed here, gap = full MMA block.
        // Safe: readers of buf (s+1)&1 (LDSM at stage s-1) all completed before sync(s).
        if (s + 1 < KT) stsB(s + 1);
    }

    const int quad = lane >> 2, tq = lane & 3;
    const int rowsb = cnt - mtile * 128;
    #pragma unroll
    for (int mt = 0; mt < 2; mt++)
        #pragma unroll
        for (int nt = 0; nt < 4; nt++)
            #pragma unroll
            for (int hr = 0; hr < 2; hr++) {
                int row = wm * 32 + mt * 16 + quad + hr * 8;
                if (row < rowsb) {
                    int c = wn * 32 + nt * 8 + tq * 2;
                    float ga = cg[mt][nt][hr * 2], gb = cg[mt][nt][hr * 2 + 1];
                    float ua = cu[mt][nt][hr * 2], ub = cu[mt][nt][hr * 2 + 1];
                    float ha = ua * (ga / (1.f + __expf(-ga)));
                    float hb = ub * (gb / (1.f + __expf(-gb)));
                    *(__half2*)(g_h + (size_t)(m0g + row) * DFF + n0 + c) =
                        __floats2half2_rn(ha, hb);
                }
            }
}

// ---------------- kernel 4: down GEMM split-K partials ----------------
// grid: (x = mtile, y = n-tile, z = expert*NSPLIT + split)
__global__ void __launch_bounds__(256, 2)
moe_down_part(const float* __restrict__ wd) {
    extern __shared__ char smem[];
    const int split = blockIdx.z & (NSPLIT - 1), e = blockIdx.z / NSPLIT;
    const int seg = g_off[e], cnt = g_off[e + 1] - seg;
    const int mtile = blockIdx.x;
    if (mtile * 128 >= cnt) return;
    const int m0g = seg + mtile * 128, n0 = blockIdx.y * 64;
    const int kbase = split * (DFF / NSPLIT);

    const int tid = threadIdx.x, warp = tid >> 5, lane = tid & 31;
    const int wm = warp >> 1, wn = warp & 1;
    const uint32_t sb = s2u(smem);

    const float* wdp = wd + (size_t)e * DFF * DMODEL + n0;

    auto stageA = [&](int s) {
        int slot = s % 3, k0 = kbase + s * 32;
        #pragma unroll
        for (int i = 0; i < 2; i++) {
            int id = tid + i * 256;
            int r = id >> 2, c = id & 3;
            bool ok = (mtile * 128 + r) < cnt;
            const __half* src = ok ? g_h + (size_t)(m0g + r) * DFF + k0 + c * 8 : g_h;
            cpa(sb + G2_A + slot * 10240 + r * 80 + c * 16, src, ok ? 16 : 0);
        }
        cp_commit();
    };
    float4 rb[2][2];                              // prefetch distance 2
    auto ldB = [&](int s, int which) {
        int k0 = kbase + s * 32;
        #pragma unroll
        for (int i = 0; i < 2; i++) {
            int id = tid + i * 256;
            int r = id >> 4, c = id & 15;
            rb[which][i] = __ldg((const float4*)(wdp + (size_t)(k0 + r) * DMODEL + c * 4));
        }
    };
    auto stsB = [&](int s, int which) {
        char* b16 = smem + G2_B16 + (s & 1) * 4608;
        #pragma unroll
        for (int i = 0; i < 2; i++)
            sts_f4h(b16, tid + i * 256, rb[which][i]);
    };

    ldB(0, 0);
    ldB(1, 1);
    stageA(0);
    stageA(1);
    stsB(0, 0);                                   // B(0) -> buf0 before first sync

    float acc[2][4][4] = {};
    const int KT = (DFF / NSPLIT) / 32;           // 32 stages
    for (int s = 0; s < KT; s++) {
        const int b1 = s & 1, slot = s % 3;
        cp_wait1();
        __syncthreads();
        if (s + 2 < KT) ldB(s + 2, s & 1);        // rb[s&1] consumed by stsB(s) already
        if (s + 2 < KT) stageA(s + 2);
        else cp_commit();
        uint32_t sA = sb + G2_A + slot * 10240;
        uint32_t sB = sb + G2_B16 + b1 * 4608;
        #pragma unroll
        for (int ks = 0; ks < 2; ks++) {
            uint32_t a[2][4], bb[8];
            #pragma unroll
            for (int mt = 0; mt < 2; mt++) {
                int row = wm * 32 + mt * 16 + (lane & 15);
                int col = ks * 16 + (lane >> 4) * 8;
                ldsm4(a[mt], sA + row * 80 + col * 2);
            }
            #pragma unroll
            for (int h = 0; h < 2; h++) {
                int kr = ks * 16 + (lane & 15);
                int nc = wn * 32 + h * 16 + (lane >> 4) * 8;
                ldsm4t(&bb[h * 4], sB + kr * 144 + nc * 2);
            }
            #pragma unroll
            for (int mt = 0; mt < 2; mt++)
                #pragma unroll
                for (int nt = 0; nt < 4; nt++)
                    mma16(acc[mt][nt], a[mt], bb[nt * 2], bb[nt * 2 + 1]);
        }
        // late STS of B(s+1) from rb[(s+1)&1]; LDG->use gap ~1.5 stages
        if (s + 1 < KT) stsB(s + 1, (s + 1) & 1);
    }

    const int quad = lane >> 2, tq = lane & 3;
    const int rowsb = cnt - mtile * 128;
    #pragma unroll
    for (int mt = 0; mt < 2; mt++)
        #pragma unroll
        for (int nt = 0; nt < 4; nt++)
            #pragma unroll
            for (int hr = 0; hr < 2; hr++) {
                int row = wm * 32 + mt * 16 + quad + hr * 8;
                if (row < rowsb) {
                    int c = wn * 32 + nt * 8 + tq * 2;
                    float2 v = make_float2(acc[mt][nt][hr * 2], acc[mt][nt][hr * 2 + 1]);
                    *(float2*)(&g_part[split][m0g + row][n0 + c]) = v;
                }
            }
}

// ---------------- kernel 5: reduce partials + scatter ----------------
__global__ void moe_reduce(float* __restrict__ out) {
    int t = blockIdx.x, d = threadIdx.x * 4;
    float4 a = *(const float4*)(&g_part[0][t][d]);
    float4 b = *(const float4*)(&g_part[1][t][d]);
    float4 c = *(const float4*)(&g_part[2][t][d]);
    float4 e = *(const float4*)(&g_part[3][t][d]);
    float4 r;
    r.x = (a.x + b.x) + (c.x + e.x);
    r.y = (a.y + b.y) + (c.y + e.y);
    r.z = (a.z + b.z) + (c.z + e.z);
    r.w = (a.w + b.w) + (c.w + e.w);
    *(float4*)(out + (size_t)g_perm[t] * DMODEL + d) = r;
}

// ---------------- launch ----------------
extern "C" void kernel_launch(void* const* d_in, const int* in_sizes, int n_in,
                              void* d_out, int out_size) {
    const float* x  = (const float*)d_in[0];
    const void*  ei = d_in[1];
    const float* wg = (const float*)d_in[2];
    const float* wu = (const float*)d_in[3];
    const float* wd = (const float*)d_in[4];
    float* out = (float*)d_out;

    cudaFuncSetAttribute(moe_gateup, cudaFuncAttributeMaxDynamicSharedMemorySize, G1_SMEM);
    cudaFuncSetAttribute(moe_down_part, cudaFuncAttributeMaxDynamicSharedMemorySize, G2_SMEM);

    moe_build_perm<<<1, 256>>>(ei);
    moe_gather<<<TTOK, 256>>>(x);
    moe_gateup<<<dim3(TTOK / 128, DFF / 64, NE), 256, G1_SMEM>>>(wg, wu);
    moe_down_part<<<dim3(TTOK / 128, DMODEL / 64, NE * NSPLIT), 256, G2_SMEM>>>(wd);
    moe_reduce<<<TTOK, 256>>>(out);
}

// round 9
// speedup vs baseline: 1.2972x; 1.2972x over previous
#include <cuda_runtime.h>
#include <cuda_fp16.h>
#include <cstdint>

#define NE 8
#define DMODEL 1024
#define DFF 4096
#define TTOK 2048
#define NSPLIT 4

// ---------------- scratch ----------------
__device__ int g_perm[TTOK];
__device__ int g_off[NE + 1];
__device__ __align__(16) __half g_x16[(size_t)TTOK * DMODEL];
__device__ __align__(16) __half g_h[(size_t)TTOK * DFF];
__device__ __align__(16) float g_part[NSPLIT][TTOK][DMODEL];

// ---------------- helpers ----------------
__device__ __forceinline__ uint32_t s2u(const void* p) {
    return (uint32_t)__cvta_generic_to_shared(p);
}
__device__ __forceinline__ void cpa(uint32_t d, const void* s, int sz) {
    asm volatile("cp.async.cg.shared.global [%0], [%1], 16, %2;" :: "r"(d), "l"(s), "r"(sz));
}
__device__ __forceinline__ void cp_commit() {
    asm volatile("cp.async.commit_group;");
}
__device__ __forceinline__ void cp_wait1() {
    asm volatile("cp.async.wait_group 1;");
}
__device__ __forceinline__ void ldsm4(uint32_t* r, uint32_t a) {
    asm volatile("ldmatrix.sync.aligned.m8n8.x4.shared.b16 {%0,%1,%2,%3}, [%4];"
                 : "=r"(r[0]), "=r"(r[1]), "=r"(r[2]), "=r"(r[3]) : "r"(a));
}
__device__ __forceinline__ void ldsm4t(uint32_t* r, uint32_t a) {
    asm volatile("ldmatrix.sync.aligned.m8n8.x4.trans.shared.b16 {%0,%1,%2,%3}, [%4];"
                 : "=r"(r[0]), "=r"(r[1]), "=r"(r[2]), "=r"(r[3]) : "r"(a));
}
__device__ __forceinline__ void mma16(float* c, const uint32_t* a, uint32_t b0, uint32_t b1) {
    asm volatile("mma.sync.aligned.m16n8k16.row.col.f32.f16.f16.f32 "
                 "{%0,%1,%2,%3},{%4,%5,%6,%7},{%8,%9},{%0,%1,%2,%3};"
                 : "+f"(c[0]), "+f"(c[1]), "+f"(c[2]), "+f"(c[3])
                 : "r"(a[0]), "r"(a[1]), "r"(a[2]), "r"(a[3]), "r"(b0), "r"(b1));
}
__device__ __forceinline__ void sts_f4h(char* base, int id, float4 v) {
    int r = id >> 4, c = id & 15;
    __half2* d = (__half2*)(base + r * 144 + c * 8);
    d[0] = __floats2half2_rn(v.x, v.y);
    d[1] = __floats2half2_rn(v.z, v.w);
}

// ---------------- kernel 1: bucket tokens by expert ----------------
__global__ void moe_build_perm(const void* eidx_raw) {
    __shared__ int cnt[NE], base[NE], nz;
    int t = threadIdx.x;
    if (t < NE) cnt[t] = 0;
    if (t == 0) nz = 0;
    __syncthreads();
    const int* i32 = (const int*)eidx_raw;
    for (int i = t; i < TTOK / 2; i += blockDim.x)
        if (i32[2 * i + 1] != 0) atomicOr(&nz, 1);
    __syncthreads();
    bool is64 = (nz == 0);
    const long long* i64 = (const long long*)eidx_raw;
    for (int i = t; i < TTOK; i += blockDim.x)
        atomicAdd(&cnt[is64 ? (int)i64[i] : i32[i]], 1);
    __syncthreads();
    if (t == 0) {
        int s = 0;
        for (int e = 0; e < NE; e++) { g_off[e] = s; base[e] = s; s += cnt[e]; }
        g_off[NE] = s;
    }
    __syncthreads();
    for (int i = t; i < TTOK; i += blockDim.x) {
        int e = is64 ? (int)i64[i] : i32[i];
        g_perm[atomicAdd(&base[e], 1)] = i;
    }
}

// ---------------- kernel 2: gather + fp16 convert ----------------
__global__ void moe_gather(const float* __restrict__ x) {
    int src = g_perm[blockIdx.x];
    float4 v = ((const float4*)(x + (size_t)src * DMODEL))[threadIdx.x];
    __half2* d = (__half2*)(g_x16 + (size_t)blockIdx.x * DMODEL + threadIdx.x * 4);
    d[0] = __floats2half2_rn(v.x, v.y);
    d[1] = __floats2half2_rn(v.z, v.w);
}

// gemm1 (BK=32): A16 3 x 128 x 80B = 30720; BG16 2 x 4608; BU16 2 x 4608; tot 49152
#define G1_A    0
#define G1_BG16 30720
#define G1_BU16 39936
#define G1_SMEM 49152
// gemm2 (BK=64): A16 3 x 128 x 144B = 55296; B16 2 x (64 x 144B) = 18432; tot 73728
#define G2_A   0
#define G2_B16 55296
#define G2_SMEM 73728

// ---------------- kernel 3: gate+up GEMM + SwiGLU (R7 structure) ----------------
// grid: (x = n-tile, y = mtile, z = expert)
__global__ void __launch_bounds__(256, 2)
moe_gateup(const float* __restrict__ wg, const float* __restrict__ wu) {
    extern __shared__ char smem[];
    const int e = blockIdx.z, seg = g_off[e], cnt = g_off[e + 1] - seg;
    const int mtile = blockIdx.y;
    if (mtile * 128 >= cnt) return;
    const int m0g = seg + mtile * 128, n0 = blockIdx.x * 64;

    const int tid = threadIdx.x, warp = tid >> 5, lane = tid & 31;
    const int wm = warp >> 1, wn = warp & 1;
    const uint32_t sb = s2u(smem);

    const float* wgp = wg + (size_t)e * DMODEL * DFF + n0;
    const float* wup = wu + (size_t)e * DMODEL * DFF + n0;

    auto stageA = [&](int s) {
        int slot = s % 3, k0 = s * 32;
        #pragma unroll
        for (int i = 0; i < 2; i++) {
            int id = tid + i * 256;
            int r = id >> 2, c = id & 3;
            bool ok = (mtile * 128 + r) < cnt;
            const __half* src = ok ? g_x16 + (size_t)(m0g + r) * DMODEL + k0 + c * 8 : g_x16;
            cpa(sb + G1_A + slot * 10240 + r * 80 + c * 16, src, ok ? 16 : 0);
        }
        cp_commit();
    };
    float4 rg[2], ru[2];
    auto ldB = [&](int s) {
        int k0 = s * 32;
        #pragma unroll
        for (int i = 0; i < 2; i++) {
            int id = tid + i * 256;
            int r = id >> 4, c = id & 15;
            size_t off = (size_t)(k0 + r) * DFF + c * 4;
            rg[i] = __ldg((const float4*)(wgp + off));
            ru[i] = __ldg((const float4*)(wup + off));
        }
    };

    ldB(0);
    stageA(0);
    stageA(1);

    float cg[2][4][4] = {}, cu[2][4][4] = {};
    const int KT = DMODEL / 32;
    for (int s = 0; s < KT; s++) {
        const int b1 = s & 1, slot = s % 3;
        char* bg16 = smem + G1_BG16 + b1 * 4608;
        char* bu16 = smem + G1_BU16 + b1 * 4608;
        #pragma unroll
        for (int i = 0; i < 2; i++) {
            sts_f4h(bg16, tid + i * 256, rg[i]);
            sts_f4h(bu16, tid + i * 256, ru[i]);
        }
        cp_wait1();
        __syncthreads();
        if (s + 1 < KT) ldB(s + 1);
        if (s + 2 < KT) stageA(s + 2);
        else cp_commit();
        uint32_t sA = sb + G1_A + slot * 10240;
        uint32_t sG = sb + G1_BG16 + b1 * 4608;
        uint32_t sU = sb + G1_BU16 + b1 * 4608;
        #pragma unroll
        for (int ks = 0; ks < 2; ks++) {
            uint32_t a[2][4], bg[8], bu[8];
            #pragma unroll
            for (int mt = 0; mt < 2; mt++) {
                int row = wm * 32 + mt * 16 + (lane & 15);
                int col = ks * 16 + (lane >> 4) * 8;
                ldsm4(a[mt], sA + row * 80 + col * 2);
            }
            #pragma unroll
            for (int h = 0; h < 2; h++) {
                int kr = ks * 16 + (lane & 15);
                int nc = wn * 32 + h * 16 + (lane >> 4) * 8;
                ldsm4t(&bg[h * 4], sG + kr * 144 + nc * 2);
                ldsm4t(&bu[h * 4], sU + kr * 144 + nc * 2);
            }
            #pragma unroll
            for (int mt = 0; mt < 2; mt++)
                #pragma unroll
                for (int nt = 0; nt < 4; nt++) {
                    mma16(cg[mt][nt], a[mt], bg[nt * 2], bg[nt * 2 + 1]);
                    mma16(cu[mt][nt], a[mt], bu[nt * 2], bu[nt * 2 + 1]);
                }
        }
    }

    const int quad = lane >> 2, tq = lane & 3;
    const int rowsb = cnt - mtile * 128;
    #pragma unroll
    for (int mt = 0; mt < 2; mt++)
        #pragma unroll
        for (int nt = 0; nt < 4; nt++)
            #pragma unroll
            for (int hr = 0; hr < 2; hr++) {
                int row = wm * 32 + mt * 16 + quad + hr * 8;
                if (row < rowsb) {
                    int c = wn * 32 + nt * 8 + tq * 2;
                    float ga = cg[mt][nt][hr * 2], gb = cg[mt][nt][hr * 2 + 1];
                    float ua = cu[mt][nt][hr * 2], ub = cu[mt][nt][hr * 2 + 1];
                    float ha = ua * (ga / (1.f + __expf(-ga)));
                    float hb = ub * (gb / (1.f + __expf(-gb)));
                    *(__half2*)(g_h + (size_t)(m0g + row) * DFF + n0 + c) =
                        __floats2half2_rn(ha, hb);
                }
            }
}

// ---------------- kernel 4: down GEMM split-K partials (BK=64) ----------------
// grid: (x = n-tile, y = mtile, z = expert*NSPLIT + split)
__global__ void __launch_bounds__(256, 2)
moe_down_part(const float* __restrict__ wd) {
    extern __shared__ char smem[];
    const int split = blockIdx.z & (NSPLIT - 1), e = blockIdx.z / NSPLIT;
    const int seg = g_off[e], cnt = g_off[e + 1] - seg;
    const int mtile = blockIdx.y;
    if (mtile * 128 >= cnt) return;
    const int m0g = seg + mtile * 128, n0 = blockIdx.x * 64;
    const int kbase = split * (DFF / NSPLIT);

    const int tid = threadIdx.x, warp = tid >> 5, lane = tid & 31;
    const int wm = warp >> 1, wn = warp & 1;
    const uint32_t sb = s2u(smem);

    const float* wdp = wd + (size_t)e * DFF * DMODEL + n0;

    // A stage: 128 rows x 64 halfs (144B padded stride), 1024 chunks of 16B
    auto stageA = [&](int s) {
        int slot = s % 3, k0 = kbase + s * 64;
        #pragma unroll
        for (int i = 0; i < 4; i++) {
            int id = tid + i * 256;
            int r = id >> 3, c = id & 7;
            bool ok = (mtile * 128 + r) < cnt;
            const __half* src = ok ? g_h + (size_t)(m0g + r) * DFF + k0 + c * 8 : g_h;
            cpa(sb + G2_A + slot * 18432 + r * 144 + c * 16, src, ok ? 16 : 0);
        }
        cp_commit();
    };
    // B: 64 rows x 64 fp32 per stage = 1024 float4, 4 per thread
    float4 rb[4];
    auto ldB = [&](int s) {
        int k0 = kbase + s * 64;
        #pragma unroll
        for (int i = 0; i < 4; i++) {
            int id = tid + i * 256;
            int r = id >> 4, c = id & 15;
            rb[i] = __ldg((const float4*)(wdp + (size_t)(k0 + r) * DMODEL + c * 4));
        }
    };
    auto stsB = [&](int s) {
        char* b16 = smem + G2_B16 + (s & 1) * 9216;
        #pragma unroll
        for (int i = 0; i < 4; i++)
            sts_f4h(b16, tid + i * 256, rb[i]);
    };

    ldB(0);
    stageA(0);
    stageA(1);

    float acc[2][4][4] = {};
    const int KT = (DFF / NSPLIT) / 64;           // 16 stages
    for (int s = 0; s < KT; s++) {
        const int b1 = s & 1, slot = s % 3;
        stsB(s);                                  // from regs loaded at s-1
        cp_wait1();
        __syncthreads();
        if (s + 1 < KT) ldB(s + 1);
        if (s + 2 < KT) stageA(s + 2);
        else cp_commit();
        uint32_t sA = sb + G2_A + slot * 18432;
        uint32_t sB = sb + G2_B16 + b1 * 9216;
        #pragma unroll
        for (int ks = 0; ks < 4; ks++) {
            uint32_t a[2][4], bb[8];
            #pragma unroll
            for (int mt = 0; mt < 2; mt++) {
                int row = wm * 32 + mt * 16 + (lane & 15);
                int col = ks * 16 + (lane >> 4) * 8;
                ldsm4(a[mt], sA + row * 144 + col * 2);
            }
            #pragma unroll
            for (int h = 0; h < 2; h++) {
                int kr = ks * 16 + (lane & 15);
                int nc = wn * 32 + h * 16 + (lane >> 4) * 8;
                ldsm4t(&bb[h * 4], sB + kr * 144 + nc * 2);
            }
            #pragma unroll
            for (int mt = 0; mt < 2; mt++)
                #pragma unroll
                for (int nt = 0; nt < 4; nt++)
                    mma16(acc[mt][nt], a[mt], bb[nt * 2], bb[nt * 2 + 1]);
        }
    }

    const int quad = lane >> 2, tq = lane & 3;
    const int rowsb = cnt - mtile * 128;
    #pragma unroll
    for (int mt = 0; mt < 2; mt++)
        #pragma unroll
        for (int nt = 0; nt < 4; nt++)
            #pragma unroll
            for (int hr = 0; hr < 2; hr++) {
                int row = wm * 32 + mt * 16 + quad + hr * 8;
                if (row < rowsb) {
                    int c = wn * 32 + nt * 8 + tq * 2;
                    float2 v = make_float2(acc[mt][nt][hr * 2], acc[mt][nt][hr * 2 + 1]);
                    *(float2*)(&g_part[split][m0g + row][n0 + c]) = v;
                }
            }
}

// ---------------- kernel 5: reduce partials + scatter ----------------
__global__ void moe_reduce(float* __restrict__ out) {
    int t = blockIdx.x, d = threadIdx.x * 4;
    float4 a = *(const float4*)(&g_part[0][t][d]);
    float4 b = *(const float4*)(&g_part[1][t][d]);
    float4 c = *(const float4*)(&g_part[2][t][d]);
    float4 e = *(const float4*)(&g_part[3][t][d]);
    float4 r;
    r.x = (a.x + b.x) + (c.x + e.x);
    r.y = (a.y + b.y) + (c.y + e.y);
    r.z = (a.z + b.z) + (c.z + e.z);
    r.w = (a.w + b.w) + (c.w + e.w);
    *(float4*)(out + (size_t)g_perm[t] * DMODEL + d) = r;
}

// ---------------- launch ----------------
extern "C" void kernel_launch(void* const* d_in, const int* in_sizes, int n_in,
                              void* d_out, int out_size) {
    const float* x  = (const float*)d_in[0];
    const void*  ei = d_in[1];
    const float* wg = (const float*)d_in[2];
    const float* wu = (const float*)d_in[3];
    const float* wd = (const float*)d_in[4];
    float* out = (float*)d_out;

    cudaFuncSetAttribute(moe_gateup, cudaFuncAttributeMaxDynamicSharedMemorySize, G1_SMEM);
    cudaFuncSetAttribute(moe_down_part, cudaFuncAttributeMaxDynamicSharedMemorySize, G2_SMEM);

    moe_build_perm<<<1, 256>>>(ei);
    moe_gather<<<TTOK, 256>>>(x);
    moe_gateup<<<dim3(DFF / 64, TTOK / 128, NE), 256, G1_SMEM>>>(wg, wu);
    moe_down_part<<<dim3(DMODEL / 64, TTOK / 128, NE * NSPLIT), 256, G2_SMEM>>>(wd);
    moe_reduce<<<TTOK, 256>>>(out);
}